// round 5
// baseline (speedup 1.0000x reference)
#include <cuda_runtime.h>
#include <cuda_bf16.h>
#include <cstdint>
#include <math.h>

// ---------------------------------------------------------------------------
// Problem constants
// ---------------------------------------------------------------------------
#define B_  8
#define L_  2048
#define C_  512
#define CI_ 256
#define MT_ 16384   // B_*L_

typedef __nv_bfloat16 bf16;

// ---------------------------------------------------------------------------
// Scratch (__device__ globals; allocation-free)
// ---------------------------------------------------------------------------
__device__ bf16  g_inH [(size_t)MT_ * C_];           // inputs hi  [bl][c]
__device__ bf16  g_inL [(size_t)MT_ * C_];           // inputs lo
__device__ bf16  g_xpH [(size_t)MT_ * CI_];          // x_proj hi  [bl][i]
__device__ bf16  g_xpL [(size_t)MT_ * CI_];
__device__ bf16  g_ypH [(size_t)MT_ * CI_];
__device__ bf16  g_ypL [(size_t)MT_ * CI_];
__device__ bf16  g_otH [(size_t)C_ * MT_];           // o_proj^T hi [c][bl]
__device__ bf16  g_otL [(size_t)C_ * MT_];
__device__ float g_scores[(size_t)B_ * L_ * L_];     // f32 logits
__device__ bf16  g_atH [(size_t)B_ * L_ * L_];       // attn hi [b][l][m]
__device__ bf16  g_atL [(size_t)B_ * L_ * L_];
__device__ bf16  g_wxtH[CI_ * C_], g_wxtL[CI_ * C_]; // WxT [i][c]
__device__ bf16  g_wytH[CI_ * C_], g_wytL[CI_ * C_];
__device__ bf16  g_wotH[C_ * C_],  g_wotL[C_ * C_];  // WoT [d][c]

// ---------------------------------------------------------------------------
// helpers
// ---------------------------------------------------------------------------
__device__ __forceinline__ uint32_t smem_u32(const void* p) {
    uint32_t a;
    asm("{ .reg .u64 t; cvta.to.shared.u64 t, %1; cvt.u32.u64 %0, t; }"
        : "=r"(a) : "l"(p));
    return a;
}
__device__ __forceinline__ void splitf(float v, bf16& h, bf16& l) {
    h = __float2bfloat16_rn(v);
    l = __float2bfloat16_rn(v - __bfloat162float(h));
}
__device__ __forceinline__ uint32_t pack2(bf16 a, bf16 b) {
    return (uint32_t)__bfloat16_as_ushort(a) |
           ((uint32_t)__bfloat16_as_ushort(b) << 16);
}

#define CP16(dst, src) \
    asm volatile("cp.async.cg.shared.global [%0], [%1], 16;" :: "r"(dst), "l"(src) : "memory")
#define CP_COMMIT() asm volatile("cp.async.commit_group;" ::: "memory")
#define CP_WAIT(n)  asm volatile("cp.async.wait_group %0;" :: "n"(n) : "memory")

#define LDSM_X4(r, a) \
    asm volatile("ldmatrix.sync.aligned.m8n8.x4.shared.b16 {%0,%1,%2,%3}, [%4];" \
        : "=r"((r)[0]), "=r"((r)[1]), "=r"((r)[2]), "=r"((r)[3]) : "r"(a))

__device__ __forceinline__ void mma_bf16(float* d, const uint32_t* a, const uint32_t* b) {
    asm volatile(
        "mma.sync.aligned.m16n8k16.row.col.f32.bf16.bf16.f32 "
        "{%0,%1,%2,%3}, {%4,%5,%6,%7}, {%8,%9}, {%0,%1,%2,%3};"
        : "+f"(d[0]), "+f"(d[1]), "+f"(d[2]), "+f"(d[3])
        : "r"(a[0]), "r"(a[1]), "r"(a[2]), "r"(a[3]), "r"(b[0]), "r"(b[1]));
}

// ---------------------------------------------------------------------------
// 3-term split-bf16 GEMM: D[M,N] = (AH+AL)[M,K] @ (BH+BL)[N,K]^T, K-major.
// Block tile 128 x NT (NT=256), K-chunk 32, 2*NT/64... = 16 warps (4M x NT/64 N),
// warp tile 32x64, 2-stage cp.async ring, 80B-padded SMEM rows (conflict-free).
// EPI: 0 = f32 store; 1 = +bias[n], write bf16 H/L; 2 = +bias[m], write H/L;
//      3 = +residual(f32), write f32.
// ---------------------------------------------------------------------------
#define ROWB 80u

template<int KTOT, int EPI, int NT>
struct GemmCfg {
    static constexpr int  THREADS = 2 * NT;            // 512 for NT=256
    static constexpr uint32_t TILE_A = 128u * ROWB;    // 10240
    static constexpr uint32_t TILE_B = (uint32_t)NT * ROWB;
    static constexpr uint32_t STAGE  = 2 * TILE_A + 2 * TILE_B;
    static constexpr uint32_t SMEM   = 2 * STAGE;
};

template<int KTOT, int EPI, int NT>
__device__ __forceinline__ void stage_copy(
    uint32_t stage,
    const bf16* __restrict__ AH, const bf16* __restrict__ AL, int ldA, int m0,
    const bf16* __restrict__ BH, const bf16* __restrict__ BL, int ldB, int n0,
    int k0, int tid)
{
    using Cfg = GemmCfg<KTOT, EPI, NT>;
    // A tiles: 128 rows x 4 chunks of 16B, hi + lo
    #pragma unroll
    for (int j = 0; j < 512 / Cfg::THREADS; ++j) {
        const int seg = tid + Cfg::THREADS * j;   // 0..511
        const int row = seg >> 2, c = seg & 3;
        const size_t so = (size_t)(m0 + row) * ldA + k0 + c * 8;
        const uint32_t off = row * ROWB + c * 16u;
        CP16(stage + off, AH + so);
        CP16(stage + Cfg::TILE_A + off, AL + so);
    }
    // B tiles: NT rows x 4 chunks, hi + lo
    #pragma unroll
    for (int j = 0; j < (NT * 4) / Cfg::THREADS; ++j) {
        const int seg = tid + Cfg::THREADS * j;   // 0..NT*4-1
        const int row = seg >> 2, c = seg & 3;
        const size_t so = (size_t)(n0 + row) * ldB + k0 + c * 8;
        const uint32_t off = row * ROWB + c * 16u;
        CP16(stage + 2 * Cfg::TILE_A + off, BH + so);
        CP16(stage + 2 * Cfg::TILE_A + Cfg::TILE_B + off, BL + so);
    }
}

template<int KTOT, int EPI, int NT>
__global__ __launch_bounds__(GemmCfg<KTOT, EPI, NT>::THREADS, 1) void gemmHL(
    const bf16* __restrict__ AH, const bf16* __restrict__ AL, long long sA, int ldA,
    const bf16* __restrict__ BH, const bf16* __restrict__ BL, long long sB, int ldB,
    float* __restrict__ Cf, bf16* __restrict__ CH, bf16* __restrict__ CL,
    long long sC, int ldC,
    const float* __restrict__ aux, long long sAux)
{
    using Cfg = GemmCfg<KTOT, EPI, NT>;
    extern __shared__ char smem[];
    const uint32_t smem_base = smem_u32(smem);

    const int tid  = threadIdx.x;
    const int wid  = tid >> 5;
    const int lane = tid & 31;
    const int g    = lane >> 2;
    const int t4   = lane & 3;
    const int wm   = (wid & 3) * 32;   // warp M offset
    const int wn   = (wid >> 2) * 64;  // warp N offset (0..NT-64)

    const int bz = blockIdx.z;
    const int m0 = blockIdx.y * 128;
    const int n0 = blockIdx.x * NT;
    const bf16* aH = AH + (size_t)bz * sA;
    const bf16* aL = AL + (size_t)bz * sA;
    const bf16* bH = BH + (size_t)bz * sB;
    const bf16* bL = BL + (size_t)bz * sB;

    // per-lane ldmatrix base offsets (bytes)
    const uint32_t aoff = (uint32_t)((wm + (lane & 7) + ((lane >> 3) & 1) * 8) * ROWB
                                     + (lane >> 4) * 16);
    const uint32_t boff = (uint32_t)((wn + (lane & 7) + ((lane >> 4) & 1) * 8) * ROWB
                                     + ((lane >> 3) & 1) * 16);

    float acc[2][8][4] = {};
    constexpr int NC = KTOT / 32;

    stage_copy<KTOT, EPI, NT>(smem_base, aH, aL, ldA, m0, bH, bL, ldB, n0, 0, tid);
    CP_COMMIT();
    if (NC > 1) {
        stage_copy<KTOT, EPI, NT>(smem_base + Cfg::STAGE, aH, aL, ldA, m0,
                                  bH, bL, ldB, n0, 32, tid);
        CP_COMMIT();
    }

    for (int kc = 0; kc < NC; ++kc) {
        if (kc + 1 < NC) { CP_WAIT(1); } else { CP_WAIT(0); }
        __syncthreads();

        const uint32_t stage = smem_base + (uint32_t)(kc & 1) * Cfg::STAGE;
        #pragma unroll
        for (int ks = 0; ks < 2; ++ks) {
            uint32_t ah[2][4], al[2][4];
            #pragma unroll
            for (int mi = 0; mi < 2; ++mi) {
                LDSM_X4(ah[mi], stage + aoff + mi * 1280u + ks * 32u);
                LDSM_X4(al[mi], stage + Cfg::TILE_A + aoff + mi * 1280u + ks * 32u);
            }
            #pragma unroll
            for (int h = 0; h < 2; ++h) {
                uint32_t bh2[8], bl2[8];
                #pragma unroll
                for (int q = 0; q < 2; ++q) {
                    LDSM_X4(bh2 + q * 4, stage + 2u * Cfg::TILE_A + boff
                                         + (uint32_t)(h * 32 + q * 16) * ROWB + ks * 32u);
                    LDSM_X4(bl2 + q * 4, stage + 2u * Cfg::TILE_A + Cfg::TILE_B + boff
                                         + (uint32_t)(h * 32 + q * 16) * ROWB + ks * 32u);
                }
                #pragma unroll
                for (int njl = 0; njl < 4; ++njl) {
                    const int nj = h * 4 + njl;
                    const uint32_t* bhf = bh2 + njl * 2;
                    const uint32_t* blf = bl2 + njl * 2;
                    #pragma unroll
                    for (int mi = 0; mi < 2; ++mi) {
                        mma_bf16(acc[mi][nj], ah[mi], bhf);
                        mma_bf16(acc[mi][nj], ah[mi], blf);
                        mma_bf16(acc[mi][nj], al[mi], bhf);
                    }
                }
            }
        }

        if (kc + 2 < NC) {
            __syncthreads();
            stage_copy<KTOT, EPI, NT>(stage, aH, aL, ldA, m0, bH, bL, ldB, n0,
                                      (kc + 2) * 32, tid);
            CP_COMMIT();
        }
    }

    // ---- epilogue ----
    float biasr[4];
    if (EPI == 2) {
        #pragma unroll
        for (int mi = 0; mi < 2; ++mi) {
            biasr[mi * 2 + 0] = aux[m0 + wm + mi * 16 + g    ];
            biasr[mi * 2 + 1] = aux[m0 + wm + mi * 16 + g + 8];
        }
    }
    const float* R = (EPI == 3) ? (aux + (size_t)bz * sAux) : nullptr;
    float* Cfb = (EPI == 0 || EPI == 3) ? (Cf + (size_t)bz * sC) : nullptr;
    bf16* CHb = (EPI == 1 || EPI == 2) ? (CH + (size_t)bz * sC) : nullptr;
    bf16* CLb = (EPI == 1 || EPI == 2) ? (CL + (size_t)bz * sC) : nullptr;

    #pragma unroll
    for (int mi = 0; mi < 2; ++mi) {
        const int r0 = m0 + wm + mi * 16 + g;
        const int r1 = r0 + 8;
        #pragma unroll
        for (int nj = 0; nj < 8; ++nj) {
            const int col = n0 + wn + nj * 8 + 2 * t4;
            float2 v0 = make_float2(acc[mi][nj][0], acc[mi][nj][1]);
            float2 v1 = make_float2(acc[mi][nj][2], acc[mi][nj][3]);
            if (EPI == 1) {
                const float2 bb = *(const float2*)&aux[col];
                v0.x += bb.x; v0.y += bb.y; v1.x += bb.x; v1.y += bb.y;
            } else if (EPI == 2) {
                v0.x += biasr[mi * 2];     v0.y += biasr[mi * 2];
                v1.x += biasr[mi * 2 + 1]; v1.y += biasr[mi * 2 + 1];
            } else if (EPI == 3) {
                const float2 q0 = *(const float2*)&R[(size_t)r0 * ldC + col];
                const float2 q1 = *(const float2*)&R[(size_t)r1 * ldC + col];
                v0.x += q0.x; v0.y += q0.y; v1.x += q1.x; v1.y += q1.y;
            }
            if (EPI == 0 || EPI == 3) {
                *(float2*)&Cfb[(size_t)r0 * ldC + col] = v0;
                *(float2*)&Cfb[(size_t)r1 * ldC + col] = v1;
            } else {
                bf16 h0, l0, h1, l1;
                splitf(v0.x, h0, l0); splitf(v0.y, h1, l1);
                *(uint32_t*)&CHb[(size_t)r0 * ldC + col] = pack2(h0, h1);
                *(uint32_t*)&CLb[(size_t)r0 * ldC + col] = pack2(l0, l1);
                splitf(v1.x, h0, l0); splitf(v1.y, h1, l1);
                *(uint32_t*)&CHb[(size_t)r1 * ldC + col] = pack2(h0, h1);
                *(uint32_t*)&CLb[(size_t)r1 * ldC + col] = pack2(l0, l1);
            }
        }
    }
}

// ---------------------------------------------------------------------------
// Decompose inputs f32 -> bf16 hi/lo (vectorized)
// ---------------------------------------------------------------------------
__global__ __launch_bounds__(256) void decomp_inputs(const float* __restrict__ src, int n4)
{
    const int i = blockIdx.x * 256 + threadIdx.x;
    if (i >= n4) return;
    const float4 v = ((const float4*)src)[i];
    bf16 h0, h1, h2, h3, l0, l1, l2, l3;
    splitf(v.x, h0, l0); splitf(v.y, h1, l1);
    splitf(v.z, h2, l2); splitf(v.w, h3, l3);
    ((uint2*)g_inH)[i] = make_uint2(pack2(h0, h1), pack2(h2, h3));
    ((uint2*)g_inL)[i] = make_uint2(pack2(l0, l1), pack2(l2, l3));
}

// ---------------------------------------------------------------------------
// Transpose + decompose weights: src[R][Cc] f32 -> H/L[Cc][R] bf16
// ---------------------------------------------------------------------------
__global__ void transposeHL(const float* __restrict__ src,
                            bf16* __restrict__ H, bf16* __restrict__ L,
                            int R, int Cc)
{
    __shared__ float tbuf[32][33];
    const int bx = blockIdx.x * 32;
    const int by = blockIdx.y * 32;
    const int x = threadIdx.x, y = threadIdx.y;   // 32 x 8
    #pragma unroll
    for (int d = 0; d < 32; d += 8)
        tbuf[y + d][x] = src[(size_t)(by + y + d) * Cc + bx + x];
    __syncthreads();
    #pragma unroll
    for (int d = 0; d < 32; d += 8) {
        bf16 h, l;
        splitf(tbuf[x][y + d], h, l);
        H[(size_t)(bx + y + d) * R + by + x] = h;
        L[(size_t)(bx + y + d) * R + by + x] = l;
    }
}

// ---------------------------------------------------------------------------
// Softmax over batch axis, f32 logits -> bf16 hi/lo attn
// ---------------------------------------------------------------------------
__global__ __launch_bounds__(256) void softmax_batch_HL()
{
    const size_t idx = ((size_t)blockIdx.x * 256 + threadIdx.x) * 2;  // pairs
    const size_t stride = (size_t)L_ * L_;
    float v0[B_], v1[B_];
    float mx0 = -INFINITY, mx1 = -INFINITY;
    #pragma unroll
    for (int b = 0; b < B_; ++b) {
        const float2 p = *(const float2*)&g_scores[b * stride + idx];
        v0[b] = p.x; v1[b] = p.y;
        mx0 = fmaxf(mx0, p.x); mx1 = fmaxf(mx1, p.y);
    }
    float s0 = 0.f, s1 = 0.f;
    #pragma unroll
    for (int b = 0; b < B_; ++b) {
        v0[b] = expf(v0[b] - mx0); s0 += v0[b];
        v1[b] = expf(v1[b] - mx1); s1 += v1[b];
    }
    const float i0 = 1.f / s0, i1 = 1.f / s1;
    #pragma unroll
    for (int b = 0; b < B_; ++b) {
        bf16 h0, l0, h1, l1;
        splitf(v0[b] * i0, h0, l0);
        splitf(v1[b] * i1, h1, l1);
        *(uint32_t*)&g_atH[b * stride + idx] = pack2(h0, h1);
        *(uint32_t*)&g_atL[b * stride + idx] = pack2(l0, l1);
    }
}

// ---------------------------------------------------------------------------
// Launch: inputs, Wx, bx, Wy, by, Wo, bo
// ---------------------------------------------------------------------------
extern "C" void kernel_launch(void* const* d_in, const int* in_sizes, int n_in,
                              void* d_out, int out_size)
{
    const float* inputs = (const float*)d_in[0];
    const float* Wx = (const float*)d_in[1];
    const float* bx = (const float*)d_in[2];
    const float* Wy = (const float*)d_in[3];
    const float* by = (const float*)d_in[4];
    const float* Wo = (const float*)d_in[5];
    const float* bo = (const float*)d_in[6];
    float* out = (float*)d_out;

    void *a;
    bf16 *inH, *inL, *xpH, *xpL, *ypH, *ypL, *otH, *otL, *atH, *atL;
    bf16 *wxtH, *wxtL, *wytH, *wytL, *wotH, *wotL;
    float *sc;
    cudaGetSymbolAddress(&a, g_inH);  inH  = (bf16*)a;
    cudaGetSymbolAddress(&a, g_inL);  inL  = (bf16*)a;
    cudaGetSymbolAddress(&a, g_xpH);  xpH  = (bf16*)a;
    cudaGetSymbolAddress(&a, g_xpL);  xpL  = (bf16*)a;
    cudaGetSymbolAddress(&a, g_ypH);  ypH  = (bf16*)a;
    cudaGetSymbolAddress(&a, g_ypL);  ypL  = (bf16*)a;
    cudaGetSymbolAddress(&a, g_otH);  otH  = (bf16*)a;
    cudaGetSymbolAddress(&a, g_otL);  otL  = (bf16*)a;
    cudaGetSymbolAddress(&a, g_atH);  atH  = (bf16*)a;
    cudaGetSymbolAddress(&a, g_atL);  atL  = (bf16*)a;
    cudaGetSymbolAddress(&a, g_wxtH); wxtH = (bf16*)a;
    cudaGetSymbolAddress(&a, g_wxtL); wxtL = (bf16*)a;
    cudaGetSymbolAddress(&a, g_wytH); wytH = (bf16*)a;
    cudaGetSymbolAddress(&a, g_wytL); wytL = (bf16*)a;
    cudaGetSymbolAddress(&a, g_wotH); wotH = (bf16*)a;
    cudaGetSymbolAddress(&a, g_wotL); wotL = (bf16*)a;
    cudaGetSymbolAddress(&a, g_scores); sc = (float*)a;

    constexpr int SM1 = GemmCfg<512, 1, 256>::SMEM;
    constexpr int SM2 = GemmCfg<512, 2, 256>::SMEM;
    constexpr int SM0 = GemmCfg<256, 0, 256>::SMEM;
    constexpr int SM3 = GemmCfg<2048, 3, 256>::SMEM;
    cudaFuncSetAttribute((const void*)gemmHL<512, 1, 256>,
                         cudaFuncAttributeMaxDynamicSharedMemorySize, SM1);
    cudaFuncSetAttribute((const void*)gemmHL<512, 2, 256>,
                         cudaFuncAttributeMaxDynamicSharedMemorySize, SM2);
    cudaFuncSetAttribute((const void*)gemmHL<256, 0, 256>,
                         cudaFuncAttributeMaxDynamicSharedMemorySize, SM0);
    cudaFuncSetAttribute((const void*)gemmHL<2048, 3, 256>,
                         cudaFuncAttributeMaxDynamicSharedMemorySize, SM3);

    // 0) decompose inputs + weights
    decomp_inputs<<<(MT_ * C_ / 4 + 255) / 256, 256>>>(inputs, MT_ * C_ / 4);
    const dim3 tb(32, 8);
    transposeHL<<<dim3(CI_ / 32, C_ / 32), tb>>>(Wx, wxtH, wxtL, C_, CI_);
    transposeHL<<<dim3(CI_ / 32, C_ / 32), tb>>>(Wy, wytH, wytL, C_, CI_);
    transposeHL<<<dim3(C_  / 32, C_ / 32), tb>>>(Wo, wotH, wotL, C_, C_);

    // 1) x_proj, y_proj: in[16384,512] @ WT[256,512]^T  (+bias[n], HL out)
    gemmHL<512, 1, 256><<<dim3(1, MT_ / 128, 1), 512, SM1>>>(
        inH, inL, 0, C_, wxtH, wxtL, 0, C_,
        nullptr, xpH, xpL, 0, CI_, bx, 0);
    gemmHL<512, 1, 256><<<dim3(1, MT_ / 128, 1), 512, SM1>>>(
        inH, inL, 0, C_, wytH, wytL, 0, C_,
        nullptr, ypH, ypL, 0, CI_, by, 0);

    // 2) o_proj^T: WoT[512,512] @ in[16384,512]^T  (+bias[m], HL out)
    gemmHL<512, 2, 256><<<dim3(MT_ / 256, C_ / 128, 1), 512, SM2>>>(
        wotH, wotL, 0, C_, inH, inL, 0, C_,
        nullptr, otH, otL, 0, MT_, bo, 0);

    // 3) scores[b] = x_proj[b] @ y_proj[b]^T  (f32 out)
    gemmHL<256, 0, 256><<<dim3(L_ / 256, L_ / 128, B_), 512, SM0>>>(
        xpH, xpL, (long long)L_ * CI_, CI_, ypH, ypL, (long long)L_ * CI_, CI_,
        sc, nullptr, nullptr, (long long)L_ * L_, L_, nullptr, 0);

    // 4) softmax over batch -> attn HL
    softmax_batch_HL<<<(L_ * L_ / 2) / 256, 256>>>();

    // 5) out[b] = inputs[b] + attn[b] @ o_proj[b]
    gemmHL<2048, 3, 256><<<dim3(C_ / 256, L_ / 128, B_), 512, SM3>>>(
        atH, atL, (long long)L_ * L_, L_, otH, otL, (long long)L_, MT_,
        out, nullptr, nullptr, (long long)L_ * C_, C_, inputs, (long long)L_ * C_);
}

// round 6
// speedup vs baseline: 1.0871x; 1.0871x over previous
#include <cuda_runtime.h>
#include <cuda_bf16.h>
#include <cstdint>
#include <math.h>

// ---------------------------------------------------------------------------
// Problem constants
// ---------------------------------------------------------------------------
#define B_  8
#define L_  2048
#define C_  512
#define CI_ 256
#define MT_ 16384   // B_*L_

typedef __nv_bfloat16 bf16;

// ---------------------------------------------------------------------------
// Scratch (__device__ globals; allocation-free)
// ---------------------------------------------------------------------------
__device__ bf16  g_inH [(size_t)MT_ * C_];           // inputs hi  [bl][c]
__device__ bf16  g_inL [(size_t)MT_ * C_];           // inputs lo
__device__ bf16  g_xyH [(size_t)MT_ * C_];           // [x_proj | y_proj] hi [bl][512]
__device__ bf16  g_xyL [(size_t)MT_ * C_];
__device__ bf16  g_otH [(size_t)C_ * MT_];           // o_proj^T hi [c][bl]
__device__ bf16  g_otL [(size_t)C_ * MT_];
__device__ float g_scores[(size_t)B_ * L_ * L_];     // f32 logits
__device__ bf16  g_atH [(size_t)B_ * L_ * L_];       // attn hi [b][l][m]
__device__ bf16  g_atL [(size_t)B_ * L_ * L_];
__device__ bf16  g_wxyH[C_ * C_], g_wxyL[C_ * C_];   // [WxT ; WyT] rows 0-511, [n][c]
__device__ bf16  g_wotH[C_ * C_], g_wotL[C_ * C_];   // WoT [d][c]
__device__ float g_bxy[C_];                          // concat(bx, by)

// ---------------------------------------------------------------------------
// helpers
// ---------------------------------------------------------------------------
__device__ __forceinline__ uint32_t smem_u32(const void* p) {
    uint32_t a;
    asm("{ .reg .u64 t; cvta.to.shared.u64 t, %1; cvt.u32.u64 %0, t; }"
        : "=r"(a) : "l"(p));
    return a;
}
__device__ __forceinline__ void splitf(float v, bf16& h, bf16& l) {
    h = __float2bfloat16_rn(v);
    l = __float2bfloat16_rn(v - __bfloat162float(h));
}
__device__ __forceinline__ uint32_t pack2(bf16 a, bf16 b) {
    return (uint32_t)__bfloat16_as_ushort(a) |
           ((uint32_t)__bfloat16_as_ushort(b) << 16);
}

#define CP16(dst, src) \
    asm volatile("cp.async.ca.shared.global [%0], [%1], 16;" :: "r"(dst), "l"(src) : "memory")
#define CP_COMMIT() asm volatile("cp.async.commit_group;" ::: "memory")
#define CP_WAIT(n)  asm volatile("cp.async.wait_group %0;" :: "n"(n) : "memory")

#define LDSM_X4(r, a) \
    asm volatile("ldmatrix.sync.aligned.m8n8.x4.shared.b16 {%0,%1,%2,%3}, [%4];" \
        : "=r"((r)[0]), "=r"((r)[1]), "=r"((r)[2]), "=r"((r)[3]) : "r"(a))

__device__ __forceinline__ void mma_bf16(float* d, const uint32_t* a, const uint32_t* b) {
    asm volatile(
        "mma.sync.aligned.m16n8k16.row.col.f32.bf16.bf16.f32 "
        "{%0,%1,%2,%3}, {%4,%5,%6,%7}, {%8,%9}, {%0,%1,%2,%3};"
        : "+f"(d[0]), "+f"(d[1]), "+f"(d[2]), "+f"(d[3])
        : "r"(a[0]), "r"(a[1]), "r"(a[2]), "r"(a[3]), "r"(b[0]), "r"(b[1]));
}

// ---------------------------------------------------------------------------
// 3-term split-bf16 GEMM: D[M,N] = (AH+AL)[M,K] @ (BH+BL)[N,K]^T, K-major.
// Block 128x128, K-chunk 32, 8 warps (4M x 2N), warp tile 32x64, 2-stage ring.
// EPI: 0 = f32 store; 1 = +bias[n], write bf16 H/L; 2 = +bias[m], write H/L;
//      3 = +residual(f32), write f32.
// ---------------------------------------------------------------------------
#define ROWB   80u
#define TILE_B 10240u
#define STAGE_B 40960u
#define SMEM_GEMM_TOTAL (2 * 40960)

template<int KTOT, int EPI>
__device__ __forceinline__ void stage_copy(
    uint32_t stage,
    const bf16* __restrict__ AH, const bf16* __restrict__ AL, int ldA, int m0,
    const bf16* __restrict__ BH, const bf16* __restrict__ BL, int ldB, int n0,
    int k0, int tid)
{
    #pragma unroll
    for (int t = 0; t < 4; ++t) {
        const bf16* base = (t == 0) ? AH : (t == 1) ? AL : (t == 2) ? BH : BL;
        const int ld   = (t < 2) ? ldA : ldB;
        const int r0   = (t < 2) ? m0  : n0;
        #pragma unroll
        for (int j = 0; j < 2; ++j) {
            const int seg = tid + 256 * j;        // 0..511
            const int row = seg >> 2;             // 0..127
            const int c   = seg & 3;              // 16B chunk
            const bf16* src = base + (size_t)(r0 + row) * ld + k0 + c * 8;
            const uint32_t dst = stage + t * TILE_B + row * ROWB + c * 16u;
            CP16(dst, src);
        }
    }
}

template<int KTOT, int EPI>
__global__ __launch_bounds__(256, 2) void gemmHL(
    const bf16* __restrict__ AH, const bf16* __restrict__ AL, long long sA, int ldA,
    const bf16* __restrict__ BH, const bf16* __restrict__ BL, long long sB, int ldB,
    float* __restrict__ Cf, bf16* __restrict__ CH, bf16* __restrict__ CL,
    long long sC, int ldC,
    const float* __restrict__ aux, long long sAux)
{
    extern __shared__ char smem[];
    const uint32_t smem_base = smem_u32(smem);

    const int tid  = threadIdx.x;
    const int wid  = tid >> 5;
    const int lane = tid & 31;
    const int g    = lane >> 2;
    const int t4   = lane & 3;
    const int wm   = (wid & 3) * 32;
    const int wn   = (wid >> 2) * 64;

    const int bz = blockIdx.z;
    const int m0 = blockIdx.y * 128;
    const int n0 = blockIdx.x * 128;
    const bf16* aH = AH + (size_t)bz * sA;
    const bf16* aL = AL + (size_t)bz * sA;
    const bf16* bH = BH + (size_t)bz * sB;
    const bf16* bL = BL + (size_t)bz * sB;

    // per-lane ldmatrix base offsets (bytes)
    const uint32_t aoff = (uint32_t)((wm + (lane & 7) + ((lane >> 3) & 1) * 8) * ROWB
                                     + (lane >> 4) * 16);
    const uint32_t boff = (uint32_t)((wn + (lane & 7) + ((lane >> 4) & 1) * 8) * ROWB
                                     + ((lane >> 3) & 1) * 16);

    float acc[2][8][4] = {};
    constexpr int NC = KTOT / 32;

    stage_copy<KTOT, EPI>(smem_base, aH, aL, ldA, m0, bH, bL, ldB, n0, 0, tid);
    CP_COMMIT();
    if (NC > 1) {
        stage_copy<KTOT, EPI>(smem_base + STAGE_B, aH, aL, ldA, m0, bH, bL, ldB, n0, 32, tid);
        CP_COMMIT();
    }

    for (int kc = 0; kc < NC; ++kc) {
        if (kc + 1 < NC) { CP_WAIT(1); } else { CP_WAIT(0); }
        __syncthreads();

        const uint32_t stage = smem_base + (uint32_t)(kc & 1) * STAGE_B;
        #pragma unroll
        for (int ks = 0; ks < 2; ++ks) {
            uint32_t ah[2][4], al[2][4];
            #pragma unroll
            for (int mi = 0; mi < 2; ++mi) {
                LDSM_X4(ah[mi], stage + aoff + mi * 1280u + ks * 32u);
                LDSM_X4(al[mi], stage + TILE_B + aoff + mi * 1280u + ks * 32u);
            }
            #pragma unroll
            for (int h = 0; h < 2; ++h) {
                uint32_t bh2[8], bl2[8];
                #pragma unroll
                for (int q = 0; q < 2; ++q) {
                    LDSM_X4(bh2 + q * 4, stage + 2u * TILE_B + boff
                                         + (uint32_t)(h * 32 + q * 16) * ROWB + ks * 32u);
                    LDSM_X4(bl2 + q * 4, stage + 3u * TILE_B + boff
                                         + (uint32_t)(h * 32 + q * 16) * ROWB + ks * 32u);
                }
                #pragma unroll
                for (int njl = 0; njl < 4; ++njl) {
                    const int nj = h * 4 + njl;
                    const uint32_t* bhf = bh2 + njl * 2;
                    const uint32_t* blf = bl2 + njl * 2;
                    #pragma unroll
                    for (int mi = 0; mi < 2; ++mi) {
                        mma_bf16(acc[mi][nj], ah[mi], bhf);
                        mma_bf16(acc[mi][nj], ah[mi], blf);
                        mma_bf16(acc[mi][nj], al[mi], bhf);
                    }
                }
            }
        }

        if (kc + 2 < NC) {
            __syncthreads();
            stage_copy<KTOT, EPI>(stage, aH, aL, ldA, m0, bH, bL, ldB, n0,
                                  (kc + 2) * 32, tid);
            CP_COMMIT();
        }
    }

    // ---- epilogue ----
    float biasr[4];
    if (EPI == 2) {
        #pragma unroll
        for (int mi = 0; mi < 2; ++mi) {
            biasr[mi * 2 + 0] = aux[m0 + wm + mi * 16 + g    ];
            biasr[mi * 2 + 1] = aux[m0 + wm + mi * 16 + g + 8];
        }
    }
    const float* R = (EPI == 3) ? (aux + (size_t)bz * sAux) : nullptr;
    float* Cfb = (EPI == 0 || EPI == 3) ? (Cf + (size_t)bz * sC) : nullptr;
    bf16* CHb = (EPI == 1 || EPI == 2) ? (CH + (size_t)bz * sC) : nullptr;
    bf16* CLb = (EPI == 1 || EPI == 2) ? (CL + (size_t)bz * sC) : nullptr;

    #pragma unroll
    for (int mi = 0; mi < 2; ++mi) {
        const int r0 = m0 + wm + mi * 16 + g;
        const int r1 = r0 + 8;
        #pragma unroll
        for (int nj = 0; nj < 8; ++nj) {
            const int col = n0 + wn + nj * 8 + 2 * t4;
            float2 v0 = make_float2(acc[mi][nj][0], acc[mi][nj][1]);
            float2 v1 = make_float2(acc[mi][nj][2], acc[mi][nj][3]);
            if (EPI == 1) {
                const float2 bb = *(const float2*)&aux[col];
                v0.x += bb.x; v0.y += bb.y; v1.x += bb.x; v1.y += bb.y;
            } else if (EPI == 2) {
                v0.x += biasr[mi * 2];     v0.y += biasr[mi * 2];
                v1.x += biasr[mi * 2 + 1]; v1.y += biasr[mi * 2 + 1];
            } else if (EPI == 3) {
                const float2 q0 = *(const float2*)&R[(size_t)r0 * ldC + col];
                const float2 q1 = *(const float2*)&R[(size_t)r1 * ldC + col];
                v0.x += q0.x; v0.y += q0.y; v1.x += q1.x; v1.y += q1.y;
            }
            if (EPI == 0 || EPI == 3) {
                *(float2*)&Cfb[(size_t)r0 * ldC + col] = v0;
                *(float2*)&Cfb[(size_t)r1 * ldC + col] = v1;
            } else {
                bf16 h0, l0, h1, l1;
                splitf(v0.x, h0, l0); splitf(v0.y, h1, l1);
                *(uint32_t*)&CHb[(size_t)r0 * ldC + col] = pack2(h0, h1);
                *(uint32_t*)&CLb[(size_t)r0 * ldC + col] = pack2(l0, l1);
                splitf(v1.x, h0, l0); splitf(v1.y, h1, l1);
                *(uint32_t*)&CHb[(size_t)r1 * ldC + col] = pack2(h0, h1);
                *(uint32_t*)&CLb[(size_t)r1 * ldC + col] = pack2(l0, l1);
            }
        }
    }
}

// ---------------------------------------------------------------------------
// Decompose inputs f32 -> bf16 hi/lo (vectorized)
// ---------------------------------------------------------------------------
__global__ __launch_bounds__(256) void decomp_inputs(const float* __restrict__ src, int n4)
{
    const int i = blockIdx.x * 256 + threadIdx.x;
    if (i >= n4) return;
    const float4 v = ((const float4*)src)[i];
    bf16 h0, h1, h2, h3, l0, l1, l2, l3;
    splitf(v.x, h0, l0); splitf(v.y, h1, l1);
    splitf(v.z, h2, l2); splitf(v.w, h3, l3);
    ((uint2*)g_inH)[i] = make_uint2(pack2(h0, h1), pack2(h2, h3));
    ((uint2*)g_inL)[i] = make_uint2(pack2(l0, l1), pack2(l2, l3));
}

// ---------------------------------------------------------------------------
// Transpose + decompose weights: src[R][Cc] f32 -> H/L[Cc][R] bf16 (dst offset)
// ---------------------------------------------------------------------------
__global__ void transposeHL(const float* __restrict__ src,
                            bf16* __restrict__ H, bf16* __restrict__ L,
                            int R, int Cc)
{
    __shared__ float tbuf[32][33];
    const int bx = blockIdx.x * 32;
    const int by = blockIdx.y * 32;
    const int x = threadIdx.x, y = threadIdx.y;   // 32 x 8
    #pragma unroll
    for (int d = 0; d < 32; d += 8)
        tbuf[y + d][x] = src[(size_t)(by + y + d) * Cc + bx + x];
    __syncthreads();
    #pragma unroll
    for (int d = 0; d < 32; d += 8) {
        bf16 h, l;
        splitf(tbuf[x][y + d], h, l);
        H[(size_t)(bx + y + d) * R + by + x] = h;
        L[(size_t)(bx + y + d) * R + by + x] = l;
    }
}

// concat bx, by into g_bxy
__global__ void concat_bias(const float* __restrict__ bx, const float* __restrict__ by)
{
    const int i = threadIdx.x + blockIdx.x * 256;
    if (i < CI_) g_bxy[i] = bx[i];
    else if (i < C_) g_bxy[i] = by[i - CI_];
}

// ---------------------------------------------------------------------------
// Softmax over batch axis, f32 logits -> bf16 hi/lo attn (float4 vectorized)
// ---------------------------------------------------------------------------
__global__ __launch_bounds__(256) void softmax_batch_HL()
{
    const size_t idx = ((size_t)blockIdx.x * 256 + threadIdx.x) * 4;  // quads
    const size_t stride = (size_t)L_ * L_;
    float4 v[B_];
    float4 mx = make_float4(-INFINITY, -INFINITY, -INFINITY, -INFINITY);
    #pragma unroll
    for (int b = 0; b < B_; ++b) {
        v[b] = *(const float4*)&g_scores[b * stride + idx];
        mx.x = fmaxf(mx.x, v[b].x); mx.y = fmaxf(mx.y, v[b].y);
        mx.z = fmaxf(mx.z, v[b].z); mx.w = fmaxf(mx.w, v[b].w);
    }
    float4 s = make_float4(0.f, 0.f, 0.f, 0.f);
    #pragma unroll
    for (int b = 0; b < B_; ++b) {
        v[b].x = __expf(v[b].x - mx.x); s.x += v[b].x;
        v[b].y = __expf(v[b].y - mx.y); s.y += v[b].y;
        v[b].z = __expf(v[b].z - mx.z); s.z += v[b].z;
        v[b].w = __expf(v[b].w - mx.w); s.w += v[b].w;
    }
    const float4 inv = make_float4(1.f / s.x, 1.f / s.y, 1.f / s.z, 1.f / s.w);
    #pragma unroll
    for (int b = 0; b < B_; ++b) {
        bf16 h0, l0, h1, l1, h2, l2, h3, l3;
        splitf(v[b].x * inv.x, h0, l0);
        splitf(v[b].y * inv.y, h1, l1);
        splitf(v[b].z * inv.z, h2, l2);
        splitf(v[b].w * inv.w, h3, l3);
        *(uint2*)&g_atH[b * stride + idx] = make_uint2(pack2(h0, h1), pack2(h2, h3));
        *(uint2*)&g_atL[b * stride + idx] = make_uint2(pack2(l0, l1), pack2(l2, l3));
    }
}

// ---------------------------------------------------------------------------
// Launch: inputs, Wx, bx, Wy, by, Wo, bo
// ---------------------------------------------------------------------------
extern "C" void kernel_launch(void* const* d_in, const int* in_sizes, int n_in,
                              void* d_out, int out_size)
{
    const float* inputs = (const float*)d_in[0];
    const float* Wx = (const float*)d_in[1];
    const float* bx = (const float*)d_in[2];
    const float* Wy = (const float*)d_in[3];
    const float* by = (const float*)d_in[4];
    const float* Wo = (const float*)d_in[5];
    const float* bo = (const float*)d_in[6];
    float* out = (float*)d_out;

    void *a;
    bf16 *inH, *inL, *xyH, *xyL, *otH, *otL, *atH, *atL;
    bf16 *wxyH, *wxyL, *wotH, *wotL;
    float *sc, *bxy;
    cudaGetSymbolAddress(&a, g_inH);  inH  = (bf16*)a;
    cudaGetSymbolAddress(&a, g_inL);  inL  = (bf16*)a;
    cudaGetSymbolAddress(&a, g_xyH);  xyH  = (bf16*)a;
    cudaGetSymbolAddress(&a, g_xyL);  xyL  = (bf16*)a;
    cudaGetSymbolAddress(&a, g_otH);  otH  = (bf16*)a;
    cudaGetSymbolAddress(&a, g_otL);  otL  = (bf16*)a;
    cudaGetSymbolAddress(&a, g_atH);  atH  = (bf16*)a;
    cudaGetSymbolAddress(&a, g_atL);  atL  = (bf16*)a;
    cudaGetSymbolAddress(&a, g_wxyH); wxyH = (bf16*)a;
    cudaGetSymbolAddress(&a, g_wxyL); wxyL = (bf16*)a;
    cudaGetSymbolAddress(&a, g_wotH); wotH = (bf16*)a;
    cudaGetSymbolAddress(&a, g_wotL); wotL = (bf16*)a;
    cudaGetSymbolAddress(&a, g_scores); sc = (float*)a;
    cudaGetSymbolAddress(&a, g_bxy);  bxy  = (float*)a;

    cudaFuncSetAttribute((const void*)gemmHL<512, 1>,
                         cudaFuncAttributeMaxDynamicSharedMemorySize, SMEM_GEMM_TOTAL);
    cudaFuncSetAttribute((const void*)gemmHL<512, 2>,
                         cudaFuncAttributeMaxDynamicSharedMemorySize, SMEM_GEMM_TOTAL);
    cudaFuncSetAttribute((const void*)gemmHL<256, 0>,
                         cudaFuncAttributeMaxDynamicSharedMemorySize, SMEM_GEMM_TOTAL);
    cudaFuncSetAttribute((const void*)gemmHL<2048, 3>,
                         cudaFuncAttributeMaxDynamicSharedMemorySize, SMEM_GEMM_TOTAL);

    // 0) decompose inputs + weights; WxT into rows [0,256), WyT into rows [256,512)
    decomp_inputs<<<(MT_ * C_ / 4 + 255) / 256, 256>>>(inputs, MT_ * C_ / 4);
    const dim3 tb(32, 8);
    transposeHL<<<dim3(CI_ / 32, C_ / 32), tb>>>(Wx, wxyH, wxyL, C_, CI_);
    transposeHL<<<dim3(CI_ / 32, C_ / 32), tb>>>(Wy, wxyH + (size_t)CI_ * C_,
                                                 wxyL + (size_t)CI_ * C_, C_, CI_);
    transposeHL<<<dim3(C_  / 32, C_ / 32), tb>>>(Wo, wotH, wotL, C_, C_);
    concat_bias<<<2, 256>>>(bx, by);

    // 1) merged projection: in[16384,512] @ Wxy[512,512]^T -> xy[16384,512] (+bias)
    gemmHL<512, 1><<<dim3(C_ / 128, MT_ / 128, 1), 256, SMEM_GEMM_TOTAL>>>(
        inH, inL, 0, C_, wxyH, wxyL, 0, C_,
        nullptr, xyH, xyL, 0, C_, bxy, 0);

    // 2) o_proj^T: WoT[512,512] @ in[16384,512]^T  (+bias[m], HL out)
    gemmHL<512, 2><<<dim3(MT_ / 128, C_ / 128, 1), 256, SMEM_GEMM_TOTAL>>>(
        wotH, wotL, 0, C_, inH, inL, 0, C_,
        nullptr, otH, otL, 0, MT_, bo, 0);

    // 3) scores[b] = x_proj[b] @ y_proj[b]^T ; x = xy cols [0,256), y = cols [256,512)
    gemmHL<256, 0><<<dim3(L_ / 128, L_ / 128, B_), 256, SMEM_GEMM_TOTAL>>>(
        xyH, xyL, (long long)L_ * C_, C_,
        xyH + CI_, xyL + CI_, (long long)L_ * C_, C_,
        sc, nullptr, nullptr, (long long)L_ * L_, L_, nullptr, 0);

    // 4) softmax over batch -> attn HL
    softmax_batch_HL<<<(L_ * L_ / 4) / 256, 256>>>();

    // 5) out[b] = inputs[b] + attn[b] @ o_proj[b]
    gemmHL<2048, 3><<<dim3(C_ / 128, L_ / 128, B_), 256, SMEM_GEMM_TOTAL>>>(
        atH, atL, (long long)L_ * L_, L_, otH, otL, (long long)L_, MT_,
        out, nullptr, nullptr, (long long)L_ * C_, C_, inputs, (long long)L_ * C_);
}

// round 7
// speedup vs baseline: 1.1403x; 1.0489x over previous
#include <cuda_runtime.h>
#include <cuda_bf16.h>
#include <cstdint>
#include <math.h>

// ---------------------------------------------------------------------------
// Problem constants
// ---------------------------------------------------------------------------
#define B_  8
#define L_  2048
#define C_  512
#define CI_ 256
#define MT_ 16384   // B_*L_

typedef __nv_bfloat16 bf16;

// ---------------------------------------------------------------------------
// Scratch (__device__ globals; allocation-free)
// ---------------------------------------------------------------------------
__device__ bf16  g_inH [(size_t)MT_ * C_];           // inputs hi  [bl][c]
__device__ bf16  g_inL [(size_t)MT_ * C_];           // inputs lo
__device__ bf16  g_xyH [(size_t)MT_ * C_];           // [x_proj | y_proj] hi [bl][512]
__device__ bf16  g_xyL [(size_t)MT_ * C_];
__device__ bf16  g_otH [(size_t)C_ * MT_];           // o_proj^T hi [c][bl]
__device__ bf16  g_otL [(size_t)C_ * MT_];
__device__ float g_scores[(size_t)B_ * L_ * L_];     // f32 logits
__device__ bf16  g_atH [(size_t)B_ * L_ * L_];       // attn hi [b][l][m]
__device__ bf16  g_atL [(size_t)B_ * L_ * L_];
__device__ bf16  g_wxyH[C_ * C_], g_wxyL[C_ * C_];   // [WxT ; WyT], [n][c]
__device__ bf16  g_wotH[C_ * C_], g_wotL[C_ * C_];   // WoT [d][c]
__device__ float g_bxy[C_];                          // concat(bx, by)
__device__ float g_bo [C_];                          // bo copy

// ---------------------------------------------------------------------------
// helpers
// ---------------------------------------------------------------------------
__device__ __forceinline__ uint32_t smem_u32(const void* p) {
    uint32_t a;
    asm("{ .reg .u64 t; cvta.to.shared.u64 t, %1; cvt.u32.u64 %0, t; }"
        : "=r"(a) : "l"(p));
    return a;
}
__device__ __forceinline__ void splitf(float v, bf16& h, bf16& l) {
    h = __float2bfloat16_rn(v);
    l = __float2bfloat16_rn(v - __bfloat162float(h));
}
__device__ __forceinline__ uint32_t pack2(bf16 a, bf16 b) {
    return (uint32_t)__bfloat16_as_ushort(a) |
           ((uint32_t)__bfloat16_as_ushort(b) << 16);
}

#define CP16(dst, src) \
    asm volatile("cp.async.ca.shared.global [%0], [%1], 16;" :: "r"(dst), "l"(src) : "memory")
#define CP_COMMIT() asm volatile("cp.async.commit_group;" ::: "memory")
#define CP_WAIT(n)  asm volatile("cp.async.wait_group %0;" :: "n"(n) : "memory")

#define LDSM_X4(r, a) \
    asm volatile("ldmatrix.sync.aligned.m8n8.x4.shared.b16 {%0,%1,%2,%3}, [%4];" \
        : "=r"((r)[0]), "=r"((r)[1]), "=r"((r)[2]), "=r"((r)[3]) : "r"(a))

__device__ __forceinline__ void mma_bf16(float* d, const uint32_t* a, const uint32_t* b) {
    asm volatile(
        "mma.sync.aligned.m16n8k16.row.col.f32.bf16.bf16.f32 "
        "{%0,%1,%2,%3}, {%4,%5,%6,%7}, {%8,%9}, {%0,%1,%2,%3};"
        : "+f"(d[0]), "+f"(d[1]), "+f"(d[2]), "+f"(d[3])
        : "r"(a[0]), "r"(a[1]), "r"(a[2]), "r"(a[3]), "r"(b[0]), "r"(b[1]));
}

// ---------------------------------------------------------------------------
// SMEM layout constants (128x128 tile, K-chunk 32, 80B-padded rows, 2 stages)
// ---------------------------------------------------------------------------
#define ROWB   80u
#define TILE_B 10240u
#define STAGE_B 40960u
#define SMEM_GEMM_TOTAL (2 * 40960)

__device__ __forceinline__ void stage_copy(
    uint32_t stage,
    const bf16* __restrict__ AH, const bf16* __restrict__ AL, int ldA, int m0,
    const bf16* __restrict__ BH, const bf16* __restrict__ BL, int ldB, int n0,
    int k0, int tid)
{
    #pragma unroll
    for (int t = 0; t < 4; ++t) {
        const bf16* base = (t == 0) ? AH : (t == 1) ? AL : (t == 2) ? BH : BL;
        const int ld = (t < 2) ? ldA : ldB;
        const int r0 = (t < 2) ? m0  : n0;
        #pragma unroll
        for (int j = 0; j < 2; ++j) {
            const int seg = tid + 256 * j;        // 0..511
            const int r = seg >> 2, c = seg & 3;  // row 0..127, 16B chunk 0..3
            const bf16* src = base + (size_t)(r0 + r) * ld + k0 + c * 8;
            const uint32_t dst = stage + t * TILE_B + r * ROWB + c * 16u;
            CP16(dst, src);
        }
    }
}

// Main loop: fills acc from (AH+AL)(BH+BL)^T, 3-term split-bf16
template<int KTOT>
__device__ __forceinline__ void gemm_core(
    float acc[2][8][4],
    const bf16* __restrict__ aH, const bf16* __restrict__ aL, int ldA, int m0,
    const bf16* __restrict__ bH, const bf16* __restrict__ bL, int ldB, int n0,
    uint32_t smem_base, int tid, uint32_t aoff, uint32_t boff)
{
    constexpr int NC = KTOT / 32;

    stage_copy(smem_base, aH, aL, ldA, m0, bH, bL, ldB, n0, 0, tid);
    CP_COMMIT();
    if (NC > 1) {
        stage_copy(smem_base + STAGE_B, aH, aL, ldA, m0, bH, bL, ldB, n0, 32, tid);
        CP_COMMIT();
    }

    for (int kc = 0; kc < NC; ++kc) {
        if (kc + 1 < NC) { CP_WAIT(1); } else { CP_WAIT(0); }
        __syncthreads();

        const uint32_t stage = smem_base + (uint32_t)(kc & 1) * STAGE_B;
        #pragma unroll
        for (int ks = 0; ks < 2; ++ks) {
            uint32_t ah[2][4], al[2][4];
            #pragma unroll
            for (int mi = 0; mi < 2; ++mi) {
                LDSM_X4(ah[mi], stage + aoff + mi * 1280u + ks * 32u);
                LDSM_X4(al[mi], stage + TILE_B + aoff + mi * 1280u + ks * 32u);
            }
            #pragma unroll
            for (int h = 0; h < 2; ++h) {
                uint32_t bh2[8], bl2[8];
                #pragma unroll
                for (int q = 0; q < 2; ++q) {
                    LDSM_X4(bh2 + q * 4, stage + 2u * TILE_B + boff
                                         + (uint32_t)(h * 32 + q * 16) * ROWB + ks * 32u);
                    LDSM_X4(bl2 + q * 4, stage + 3u * TILE_B + boff
                                         + (uint32_t)(h * 32 + q * 16) * ROWB + ks * 32u);
                }
                #pragma unroll
                for (int njl = 0; njl < 4; ++njl) {
                    const int nj = h * 4 + njl;
                    const uint32_t* bhf = bh2 + njl * 2;
                    const uint32_t* blf = bl2 + njl * 2;
                    #pragma unroll
                    for (int mi = 0; mi < 2; ++mi) {
                        mma_bf16(acc[mi][nj], ah[mi], bhf);
                        mma_bf16(acc[mi][nj], ah[mi], blf);
                        mma_bf16(acc[mi][nj], al[mi], bhf);
                    }
                }
            }
        }

        if (kc + 2 < NC) {
            __syncthreads();
            stage_copy(stage, aH, aL, ldA, m0, bH, bL, ldB, n0, (kc + 2) * 32, tid);
            CP_COMMIT();
        }
    }
}

// ---------------------------------------------------------------------------
// Fused projection + o_proj^T kernel (both KTOT=512, bf16 HL outputs)
// z=0: xy = in @ Wxy^T + bxy[n]   grid (4=n, 128=m, .)
// z=1: ot = WoT @ in^T + bo[m]    grid (4=m, 128=n, .)
// ---------------------------------------------------------------------------
__global__ __launch_bounds__(256, 2) void gemm_projot()
{
    extern __shared__ char smem[];
    const uint32_t smem_base = smem_u32(smem);

    const int tid  = threadIdx.x;
    const int wid  = tid >> 5;
    const int lane = tid & 31;
    const int g    = lane >> 2;
    const int t4   = lane & 3;
    const int wm   = (wid & 3) * 32;
    const int wn   = (wid >> 2) * 64;

    const int zz = blockIdx.z;
    const int m0 = (zz == 0) ? blockIdx.y * 128 : blockIdx.x * 128;
    const int n0 = (zz == 0) ? blockIdx.x * 128 : blockIdx.y * 128;

    const bf16* aH = (zz == 0) ? g_inH  : g_wotH;
    const bf16* aL = (zz == 0) ? g_inL  : g_wotL;
    const bf16* bH = (zz == 0) ? g_wxyH : g_inH;
    const bf16* bL = (zz == 0) ? g_wxyL : g_inL;

    const uint32_t aoff = (uint32_t)((wm + (lane & 7) + ((lane >> 3) & 1) * 8) * ROWB
                                     + (lane >> 4) * 16);
    const uint32_t boff = (uint32_t)((wn + (lane & 7) + ((lane >> 4) & 1) * 8) * ROWB
                                     + ((lane >> 3) & 1) * 16);

    float acc[2][8][4] = {};
    gemm_core<512>(acc, aH, aL, C_, m0, bH, bL, C_, n0, smem_base, tid, aoff, boff);

    bf16* CH  = (zz == 0) ? g_xyH : g_otH;
    bf16* CL  = (zz == 0) ? g_xyL : g_otL;
    const int ldC = (zz == 0) ? C_ : MT_;

    #pragma unroll
    for (int mi = 0; mi < 2; ++mi) {
        const int r0 = m0 + wm + mi * 16 + g;
        const int r1 = r0 + 8;
        const float bm0 = (zz == 1) ? g_bo[r0] : 0.f;
        const float bm1 = (zz == 1) ? g_bo[r1] : 0.f;
        #pragma unroll
        for (int nj = 0; nj < 8; ++nj) {
            const int col = n0 + wn + nj * 8 + 2 * t4;
            float2 v0 = make_float2(acc[mi][nj][0], acc[mi][nj][1]);
            float2 v1 = make_float2(acc[mi][nj][2], acc[mi][nj][3]);
            if (zz == 0) {
                const float2 bb = *(const float2*)&g_bxy[col];
                v0.x += bb.x; v0.y += bb.y; v1.x += bb.x; v1.y += bb.y;
            } else {
                v0.x += bm0; v0.y += bm0; v1.x += bm1; v1.y += bm1;
            }
            bf16 h0, l0, h1, l1;
            splitf(v0.x, h0, l0); splitf(v0.y, h1, l1);
            *(uint32_t*)&CH[(size_t)r0 * ldC + col] = pack2(h0, h1);
            *(uint32_t*)&CL[(size_t)r0 * ldC + col] = pack2(l0, l1);
            splitf(v1.x, h0, l0); splitf(v1.y, h1, l1);
            *(uint32_t*)&CH[(size_t)r1 * ldC + col] = pack2(h0, h1);
            *(uint32_t*)&CL[(size_t)r1 * ldC + col] = pack2(l0, l1);
        }
    }
}

// ---------------------------------------------------------------------------
// Batched GEMMs: scores (EPI 0, f32 out) and nn_out (EPI 3, +residual f32 out)
// ---------------------------------------------------------------------------
template<int KTOT, int EPI>
__global__ __launch_bounds__(256, 2) void gemmHL(
    const bf16* __restrict__ AH, const bf16* __restrict__ AL, long long sA, int ldA,
    const bf16* __restrict__ BH, const bf16* __restrict__ BL, long long sB, int ldB,
    float* __restrict__ Cf, long long sC, int ldC,
    const float* __restrict__ aux, long long sAux)
{
    extern __shared__ char smem[];
    const uint32_t smem_base = smem_u32(smem);

    const int tid  = threadIdx.x;
    const int wid  = tid >> 5;
    const int lane = tid & 31;
    const int g    = lane >> 2;
    const int t4   = lane & 3;
    const int wm   = (wid & 3) * 32;
    const int wn   = (wid >> 2) * 64;

    const int bz = blockIdx.z;
    const int m0 = blockIdx.y * 128;
    const int n0 = blockIdx.x * 128;
    const bf16* aH = AH + (size_t)bz * sA;
    const bf16* aL = AL + (size_t)bz * sA;
    const bf16* bH = BH + (size_t)bz * sB;
    const bf16* bL = BL + (size_t)bz * sB;

    const uint32_t aoff = (uint32_t)((wm + (lane & 7) + ((lane >> 3) & 1) * 8) * ROWB
                                     + (lane >> 4) * 16);
    const uint32_t boff = (uint32_t)((wn + (lane & 7) + ((lane >> 4) & 1) * 8) * ROWB
                                     + ((lane >> 3) & 1) * 16);

    float acc[2][8][4] = {};
    gemm_core<KTOT>(acc, aH, aL, ldA, m0, bH, bL, ldB, n0, smem_base, tid, aoff, boff);

    const float* R = (EPI == 3) ? (aux + (size_t)bz * sAux) : nullptr;
    float* Cfb = Cf + (size_t)bz * sC;

    #pragma unroll
    for (int mi = 0; mi < 2; ++mi) {
        const int r0 = m0 + wm + mi * 16 + g;
        const int r1 = r0 + 8;
        #pragma unroll
        for (int nj = 0; nj < 8; ++nj) {
            const int col = n0 + wn + nj * 8 + 2 * t4;
            float2 v0 = make_float2(acc[mi][nj][0], acc[mi][nj][1]);
            float2 v1 = make_float2(acc[mi][nj][2], acc[mi][nj][3]);
            if (EPI == 3) {
                const float2 q0 = *(const float2*)&R[(size_t)r0 * ldC + col];
                const float2 q1 = *(const float2*)&R[(size_t)r1 * ldC + col];
                v0.x += q0.x; v0.y += q0.y; v1.x += q1.x; v1.y += q1.y;
            }
            *(float2*)&Cfb[(size_t)r0 * ldC + col] = v0;
            *(float2*)&Cfb[(size_t)r1 * ldC + col] = v1;
        }
    }
}

// ---------------------------------------------------------------------------
// Decompose inputs f32 -> bf16 hi/lo; block 0/1 also copy biases
// ---------------------------------------------------------------------------
__global__ __launch_bounds__(256) void decomp_inputs(
    const float* __restrict__ src, int n4,
    const float* __restrict__ bx, const float* __restrict__ by,
    const float* __restrict__ bo)
{
    const int i = blockIdx.x * 256 + threadIdx.x;
    if (i < C_) {
        g_bxy[i] = (i < CI_) ? bx[i] : by[i - CI_];
        g_bo[i]  = bo[i];
    }
    if (i >= n4) return;
    const float4 v = ((const float4*)src)[i];
    bf16 h0, h1, h2, h3, l0, l1, l2, l3;
    splitf(v.x, h0, l0); splitf(v.y, h1, l1);
    splitf(v.z, h2, l2); splitf(v.w, h3, l3);
    ((uint2*)g_inH)[i] = make_uint2(pack2(h0, h1), pack2(h2, h3));
    ((uint2*)g_inL)[i] = make_uint2(pack2(l0, l1), pack2(l2, l3));
}

// ---------------------------------------------------------------------------
// Single prep kernel: z selects Wx / Wy / Wo transpose+decompose
// ---------------------------------------------------------------------------
__global__ void prep_weights(const float* __restrict__ Wx,
                             const float* __restrict__ Wy,
                             const float* __restrict__ Wo)
{
    __shared__ float tbuf[32][33];
    const int zz = blockIdx.z;
    const int Cc = (zz == 2) ? C_ : CI_;
    if (blockIdx.x * 32 >= Cc) return;
    const float* src = (zz == 0) ? Wx : (zz == 1) ? Wy : Wo;
    bf16* H = (zz == 0) ? g_wxyH : (zz == 1) ? g_wxyH + (size_t)CI_ * C_ : g_wotH;
    bf16* L = (zz == 0) ? g_wxyL : (zz == 1) ? g_wxyL + (size_t)CI_ * C_ : g_wotL;

    const int bx = blockIdx.x * 32;
    const int by = blockIdx.y * 32;
    const int x = threadIdx.x, y = threadIdx.y;   // 32 x 8
    #pragma unroll
    for (int d = 0; d < 32; d += 8)
        tbuf[y + d][x] = src[(size_t)(by + y + d) * Cc + bx + x];
    __syncthreads();
    #pragma unroll
    for (int d = 0; d < 32; d += 8) {
        bf16 h, l;
        splitf(tbuf[x][y + d], h, l);
        H[(size_t)(bx + y + d) * C_ + by + x] = h;
        L[(size_t)(bx + y + d) * C_ + by + x] = l;
    }
}

// ---------------------------------------------------------------------------
// Softmax over batch axis, f32 logits -> bf16 hi/lo attn (float4 vectorized)
// ---------------------------------------------------------------------------
__global__ __launch_bounds__(256) void softmax_batch_HL()
{
    const size_t idx = ((size_t)blockIdx.x * 256 + threadIdx.x) * 4;
    const size_t stride = (size_t)L_ * L_;
    float4 v[B_];
    float4 mx = make_float4(-INFINITY, -INFINITY, -INFINITY, -INFINITY);
    #pragma unroll
    for (int b = 0; b < B_; ++b) {
        v[b] = *(const float4*)&g_scores[b * stride + idx];
        mx.x = fmaxf(mx.x, v[b].x); mx.y = fmaxf(mx.y, v[b].y);
        mx.z = fmaxf(mx.z, v[b].z); mx.w = fmaxf(mx.w, v[b].w);
    }
    float4 s = make_float4(0.f, 0.f, 0.f, 0.f);
    #pragma unroll
    for (int b = 0; b < B_; ++b) {
        v[b].x = __expf(v[b].x - mx.x); s.x += v[b].x;
        v[b].y = __expf(v[b].y - mx.y); s.y += v[b].y;
        v[b].z = __expf(v[b].z - mx.z); s.z += v[b].z;
        v[b].w = __expf(v[b].w - mx.w); s.w += v[b].w;
    }
    const float4 inv = make_float4(1.f / s.x, 1.f / s.y, 1.f / s.z, 1.f / s.w);
    #pragma unroll
    for (int b = 0; b < B_; ++b) {
        bf16 h0, l0, h1, l1, h2, l2, h3, l3;
        splitf(v[b].x * inv.x, h0, l0);
        splitf(v[b].y * inv.y, h1, l1);
        splitf(v[b].z * inv.z, h2, l2);
        splitf(v[b].w * inv.w, h3, l3);
        *(uint2*)&g_atH[b * stride + idx] = make_uint2(pack2(h0, h1), pack2(h2, h3));
        *(uint2*)&g_atL[b * stride + idx] = make_uint2(pack2(l0, l1), pack2(l2, l3));
    }
}

// ---------------------------------------------------------------------------
// Launch: inputs, Wx, bx, Wy, by, Wo, bo
// ---------------------------------------------------------------------------
extern "C" void kernel_launch(void* const* d_in, const int* in_sizes, int n_in,
                              void* d_out, int out_size)
{
    const float* inputs = (const float*)d_in[0];
    const float* Wx = (const float*)d_in[1];
    const float* bx = (const float*)d_in[2];
    const float* Wy = (const float*)d_in[3];
    const float* by = (const float*)d_in[4];
    const float* Wo = (const float*)d_in[5];
    const float* bo = (const float*)d_in[6];
    float* out = (float*)d_out;

    void *a;
    bf16 *xyH, *xyL, *otH, *otL, *atH, *atL;
    float *sc;
    cudaGetSymbolAddress(&a, g_xyH);  xyH  = (bf16*)a;
    cudaGetSymbolAddress(&a, g_xyL);  xyL  = (bf16*)a;
    cudaGetSymbolAddress(&a, g_otH);  otH  = (bf16*)a;
    cudaGetSymbolAddress(&a, g_otL);  otL  = (bf16*)a;
    cudaGetSymbolAddress(&a, g_atH);  atH  = (bf16*)a;
    cudaGetSymbolAddress(&a, g_atL);  atL  = (bf16*)a;
    cudaGetSymbolAddress(&a, g_scores); sc = (float*)a;

    cudaFuncSetAttribute((const void*)gemm_projot,
                         cudaFuncAttributeMaxDynamicSharedMemorySize, SMEM_GEMM_TOTAL);
    cudaFuncSetAttribute((const void*)gemmHL<256, 0>,
                         cudaFuncAttributeMaxDynamicSharedMemorySize, SMEM_GEMM_TOTAL);
    cudaFuncSetAttribute((const void*)gemmHL<2048, 3>,
                         cudaFuncAttributeMaxDynamicSharedMemorySize, SMEM_GEMM_TOTAL);

    // 0) decompose inputs (+bias copies), prep weights
    decomp_inputs<<<(MT_ * C_ / 4 + 255) / 256, 256>>>(inputs, MT_ * C_ / 4, bx, by, bo);
    prep_weights<<<dim3(16, 16, 3), dim3(32, 8)>>>(Wx, Wy, Wo);

    // 1) fused projection + o_proj^T (1024 CTAs, one tail)
    gemm_projot<<<dim3(4, 128, 2), 256, SMEM_GEMM_TOTAL>>>();

    // 2) scores[b] = x_proj[b] @ y_proj[b]^T
    gemmHL<256, 0><<<dim3(L_ / 128, L_ / 128, B_), 256, SMEM_GEMM_TOTAL>>>(
        xyH, xyL, (long long)L_ * C_, C_,
        xyH + CI_, xyL + CI_, (long long)L_ * C_, C_,
        sc, (long long)L_ * L_, L_, nullptr, 0);

    // 3) softmax over batch -> attn HL
    softmax_batch_HL<<<(L_ * L_ / 4) / 256, 256>>>();

    // 4) out[b] = inputs[b] + attn[b] @ o_proj[b]
    gemmHL<2048, 3><<<dim3(C_ / 128, L_ / 128, B_), 256, SMEM_GEMM_TOTAL>>>(
        atH, atL, (long long)L_ * L_, L_, otH, otL, (long long)L_, MT_,
        out, (long long)L_ * C_, C_, inputs, (long long)L_ * C_);
}